// round 8
// baseline (speedup 1.0000x reference)
#include <cuda_runtime.h>

// out[row] = { xc @ w_sum + b,  exp(log|xc| @ w_prod) },  xc = [x, sin(x)], D=64.
// One warp per row; lane l handles elements 2l, 2l+1 (float2 coalesced load).
// Grid-stride over rows; per-lane weights held in registers across rows.
//
// sin computed with SLEEF-style FMA polynomial (4-part pi reduction) so that
// log|sin x| has good RELATIVE accuracy near zeros of sin (MUFU.SIN does not).
// Product path uses identity exp(w . ln|a|) = 2^(w . log2|a|)  -> __log2f/exp2f.

__device__ __forceinline__ float sin_acc(float x)
{
    // k = round(x / pi) via magic-number rounding; parity from mantissa low bit.
    const float t  = fmaf(x, 0.31830988618379067f, 12582912.0f);  // 1.5*2^23
    const int   qi = __float_as_int(t);
    const float k  = t - 12582912.0f;

    // 4-part pi (SLEEF split): r = x - k*pi, relative-accurate near r = 0.
    float r = fmaf(k, -3.140625f,                   x);
    r       = fmaf(k, -9.670257568359375e-04f,      r);
    r       = fmaf(k, -6.2771141529083251953e-07f,  r);
    r       = fmaf(k, -1.2154201256553420762e-10f,  r);

    // sin(r) on [-pi/2, pi/2], ~3.5 ulp relative (SLEEF u35 coeffs)
    const float s = r * r;
    float u = 2.6083159809786593541503e-06f;
    u = fmaf(u, s, -1.9810690716840117e-04f);
    u = fmaf(u, s,  8.3330778777599334716797e-03f);
    u = fmaf(u, s, -1.6666659712791442871094e-01f);
    u = fmaf(u, s * r, r);

    // sin(x) = (-1)^k * sin(r)
    return __int_as_float(__float_as_int(u) ^ ((qi & 1) << 31));
}

__global__ __launch_bounds__(256) void myfunc_kernel(
    const float* __restrict__ x,
    const float* __restrict__ w_sum,
    const float* __restrict__ b_sum,
    const float* __restrict__ w_prod,
    float2* __restrict__ out,
    int B)
{
    const int lane   = threadIdx.x & 31;
    const int gwarp  = (blockIdx.x * blockDim.x + threadIdx.x) >> 5;
    const int nwarps = (gridDim.x * blockDim.x) >> 5;

    // Per-lane weights (lane l covers columns 2l, 2l+1; sin features at +64)
    const float2* ws2 = reinterpret_cast<const float2*>(w_sum);
    const float2* wp2 = reinterpret_cast<const float2*>(w_prod);
    const float2 wsA = ws2[lane];
    const float2 wsB = ws2[lane + 32];
    const float2 wpA = wp2[lane];
    const float2 wpB = wp2[lane + 32];
    const float  bias = *b_sum;

    for (int r = gwarp; r < B; r += nwarps) {
        const float2 v = reinterpret_cast<const float2*>(x + (size_t)r * 64)[lane];

        const float s0 = sin_acc(v.x);
        const float s1 = sin_acc(v.y);

        // linear part
        float lin = v.x * wsA.x;
        lin = fmaf(v.y, wsA.y, lin);
        lin = fmaf(s0,  wsB.x, lin);
        lin = fmaf(s1,  wsB.y, lin);

        // log-product part in base-2: lg = sum wp_j * log2|xc_j|
        float lg = __log2f(fabsf(v.x)) * wpA.x;
        lg = fmaf(__log2f(fabsf(v.y)), wpA.y, lg);
        lg = fmaf(__log2f(fabsf(s0)),  wpB.x, lg);
        lg = fmaf(__log2f(fabsf(s1)),  wpB.y, lg);

        // warp butterfly reduction of both accumulators
        #pragma unroll
        for (int off = 16; off > 0; off >>= 1) {
            lin += __shfl_xor_sync(0xFFFFFFFFu, lin, off);
            lg  += __shfl_xor_sync(0xFFFFFFFFu, lg,  off);
        }

        if (lane == 0) {
            out[r] = make_float2(lin + bias, exp2f(lg));
        }
    }
}

extern "C" void kernel_launch(void* const* d_in, const int* in_sizes, int n_in,
                              void* d_out, int out_size)
{
    const float* x      = (const float*)d_in[0];
    const float* w_sum  = (const float*)d_in[1];
    const float* b_sum  = (const float*)d_in[2];
    const float* w_prod = (const float*)d_in[3];
    float2* out = (float2*)d_out;

    const int B = in_sizes[0] / 64;

    const int threads = 256;   // 8 warps/block
    const int blocks  = 2048;  // 16384 warps, grid-stride (64 rows/warp)
    myfunc_kernel<<<blocks, threads>>>(x, w_sum, b_sum, w_prod, out, B);
}

// round 9
// speedup vs baseline: 1.6182x; 1.6182x over previous
#include <cuda_runtime.h>

// out[row] = { xc @ w_sum + b,  exp(log|xc| @ w_prod) },  xc = [x, sin(x)], D=64.
// 8 lanes per row, 8 elements (4 packed f32x2 pairs) per lane, 4 rows per warp.
// All polynomial/dot math in Blackwell packed f32x2 (FFMA2/FMUL2/FADD2).
// sin via SLEEF-style 4-part pi reduction (relative accuracy near sin zeros);
// product path: exp(w.ln|a|) = 2^(w.log2|a|) -> MUFU.LG2 (free |.|) + exp2f.

typedef unsigned long long ull;

__device__ __forceinline__ ull pk2(float lo, float hi) {
    ull r; asm("mov.b64 %0, {%1, %2};" : "=l"(r) : "f"(lo), "f"(hi)); return r;
}
__device__ __forceinline__ void upk2(ull v, float& lo, float& hi) {
    asm("mov.b64 {%0, %1}, %2;" : "=f"(lo), "=f"(hi) : "l"(v));
}
__device__ __forceinline__ ull fma2(ull a, ull b, ull c) {
    ull d; asm("fma.rn.f32x2 %0, %1, %2, %3;" : "=l"(d) : "l"(a), "l"(b), "l"(c)); return d;
}
__device__ __forceinline__ ull mul2(ull a, ull b) {
    ull d; asm("mul.rn.f32x2 %0, %1, %2;" : "=l"(d) : "l"(a), "l"(b)); return d;
}
__device__ __forceinline__ ull add2(ull a, ull b) {
    ull d; asm("add.rn.f32x2 %0, %1, %2;" : "=l"(d) : "l"(a), "l"(b)); return d;
}

__global__ __launch_bounds__(256) void myfunc_kernel(
    const float* __restrict__ x,
    const float* __restrict__ w_sum,
    const float* __restrict__ b_sum,
    const float* __restrict__ w_prod,
    float2* __restrict__ out,
    int B)
{
    const int lane  = threadIdx.x & 31;
    const int sub   = lane & 7;    // position within row (8 lanes/row)
    const int grp   = lane >> 3;   // which of the 4 rows this warp handles
    const int gwarp = (blockIdx.x * blockDim.x + threadIdx.x) >> 5;
    const int nwarps= (gridDim.x * blockDim.x) >> 5;

    // Per-lane weights: columns 8*sub .. 8*sub+7 of [x | sin(x)] features,
    // held as 4 packed pairs each.
    const ull* ws = (const ull*)w_sum;
    const ull* wp = (const ull*)w_prod;
    ull wsx[4], wss[4], wpx[4], wps[4];
    #pragma unroll
    for (int j = 0; j < 4; j++) {
        wsx[j] = ws[sub * 4 + j];
        wss[j] = ws[32 + sub * 4 + j];
        wpx[j] = wp[sub * 4 + j];
        wps[j] = wp[32 + sub * 4 + j];
    }
    const float bias = *b_sum;

    // Broadcast packed constants (hoisted, register-resident)
    const ull C_INVPI  = pk2( 0.31830988618379067f,  0.31830988618379067f);
    const ull C_MAGIC  = pk2( 12582912.0f,  12582912.0f);   // 1.5*2^23
    const ull C_NMAGIC = pk2(-12582912.0f, -12582912.0f);
    const ull P0 = pk2(-3.140625f,                  -3.140625f);
    const ull P1 = pk2(-9.670257568359375e-04f,     -9.670257568359375e-04f);
    const ull P2 = pk2(-6.2771141529083251953e-07f, -6.2771141529083251953e-07f);
    const ull P3 = pk2(-1.2154201256553420762e-10f, -1.2154201256553420762e-10f);
    const ull S0 = pk2( 2.6083159809786593541503e-06f,  2.6083159809786593541503e-06f);
    const ull S1 = pk2(-1.9810690716840117e-04f,        -1.9810690716840117e-04f);
    const ull S2 = pk2( 8.3330778777599334716797e-03f,   8.3330778777599334716797e-03f);
    const ull S3 = pk2(-1.6666659712791442871094e-01f,  -1.6666659712791442871094e-01f);

    for (int r0 = gwarp * 4; r0 < B; r0 += nwarps * 4) {
        const int row = r0 + grp;
        const ull* xr = (const ull*)(x + (size_t)row * 64) + sub * 4;
        const ulonglong2 va = ((const ulonglong2*)xr)[0];   // pairs 0,1
        const ulonglong2 vb = ((const ulonglong2*)xr)[1];   // pairs 2,3
        const ull p[4] = { va.x, va.y, vb.x, vb.y };

        ull lin = 0ull;   // packed (+0, +0)
        ull lg  = 0ull;

        #pragma unroll
        for (int j = 0; j < 4; j++) {
            const ull v = p[j];

            // ---- packed sin ----
            const ull t = fma2(v, C_INVPI, C_MAGIC);       // round(x/pi) in low mantissa
            float t0, t1; upk2(t, t0, t1);
            const int q0 = __float_as_int(t0);
            const int q1 = __float_as_int(t1);
            const ull kk = add2(t, C_NMAGIC);              // k = round(x/pi)

            ull r = fma2(kk, P0, v);                       // 4-part pi reduction
            r = fma2(kk, P1, r);
            r = fma2(kk, P2, r);
            r = fma2(kk, P3, r);

            const ull s = mul2(r, r);
            ull u = S0;
            u = fma2(u, s, S1);
            u = fma2(u, s, S2);
            u = fma2(u, s, S3);
            u = fma2(u, mul2(s, r), r);                    // |sin| up to parity sign

            // parity sign only needed for the linear dot (log uses |u|)
            const float sg0 = __int_as_float(((q0 & 1) << 31) | 0x3F800000);
            const float sg1 = __int_as_float(((q1 & 1) << 31) | 0x3F800000);
            const ull sg = pk2(sg0, sg1);

            // ---- linear dot ----
            lin = fma2(v, wsx[j], lin);
            lin = fma2(u, mul2(sg, wss[j]), lin);

            // ---- log dot (base 2), MUFU.LG2 with free |.| modifier ----
            float v0, v1, u0, u1;
            upk2(v, v0, v1);
            upk2(u, u0, u1);
            const ull lx = pk2(__log2f(fabsf(v0)), __log2f(fabsf(v1)));
            const ull ls = pk2(__log2f(fabsf(u0)), __log2f(fabsf(u1)));
            lg = fma2(lx, wpx[j], lg);
            lg = fma2(ls, wps[j], lg);
        }

        // horizontal add within packed pair, then 3-level butterfly over 8 lanes
        float l0, l1, g0, g1;
        upk2(lin, l0, l1);
        upk2(lg,  g0, g1);
        float lin_s = l0 + l1;
        float lg_s  = g0 + g1;
        #pragma unroll
        for (int off = 4; off > 0; off >>= 1) {
            lin_s += __shfl_xor_sync(0xFFFFFFFFu, lin_s, off);
            lg_s  += __shfl_xor_sync(0xFFFFFFFFu, lg_s,  off);
        }

        if (sub == 0) {
            out[row] = make_float2(lin_s + bias, exp2f(lg_s));
        }
    }
}

extern "C" void kernel_launch(void* const* d_in, const int* in_sizes, int n_in,
                              void* d_out, int out_size)
{
    const float* x      = (const float*)d_in[0];
    const float* w_sum  = (const float*)d_in[1];
    const float* b_sum  = (const float*)d_in[2];
    const float* w_prod = (const float*)d_in[3];
    float2* out = (float2*)d_out;

    const int B = in_sizes[0] / 64;   // 1048576

    const int threads = 256;   // 8 warps/block
    const int blocks  = 2048;  // 16384 warps * 4 rows/iter = 64K rows per pass
    myfunc_kernel<<<blocks, threads>>>(x, w_sum, b_sum, w_prod, out, B);
}

// round 10
// speedup vs baseline: 1.6593x; 1.0254x over previous
#include <cuda_runtime.h>

// out[row] = { xc @ w_sum + b,  exp(log|xc| @ w_prod) },  xc = [x, sin(x)], D=64.
// 8 lanes per row, 8 elements (4 packed f32x2 pairs) per lane, 4 rows per warp.
// Polynomial + linear dot in Blackwell packed f32x2 (FFMA2/FMUL2/FADD2).
// sin via SLEEF-style 3-part Cody-Waite pi reduction (relative accuracy near
// sin zeros; MUFU.SIN is not relatively accurate there). Sign applied by XOR.
// Product path: exp(w.ln|a|) = 2^(w.log2|a|) -> MUFU.LG2 (free |.|) + exp2f.

typedef unsigned long long ull;

__device__ __forceinline__ ull pk2(float lo, float hi) {
    ull r; asm("mov.b64 %0, {%1, %2};" : "=l"(r) : "f"(lo), "f"(hi)); return r;
}
__device__ __forceinline__ void upk2(ull v, float& lo, float& hi) {
    asm("mov.b64 {%0, %1}, %2;" : "=f"(lo), "=f"(hi) : "l"(v));
}
__device__ __forceinline__ ull fma2(ull a, ull b, ull c) {
    ull d; asm("fma.rn.f32x2 %0, %1, %2, %3;" : "=l"(d) : "l"(a), "l"(b), "l"(c)); return d;
}
__device__ __forceinline__ ull mul2(ull a, ull b) {
    ull d; asm("mul.rn.f32x2 %0, %1, %2;" : "=l"(d) : "l"(a), "l"(b)); return d;
}
__device__ __forceinline__ ull add2(ull a, ull b) {
    ull d; asm("add.rn.f32x2 %0, %1, %2;" : "=l"(d) : "l"(a), "l"(b)); return d;
}

__global__ __launch_bounds__(256) void myfunc_kernel(
    const float* __restrict__ x,
    const float* __restrict__ w_sum,
    const float* __restrict__ b_sum,
    const float* __restrict__ w_prod,
    float2* __restrict__ out,
    int B)
{
    const int lane  = threadIdx.x & 31;
    const int sub   = lane & 7;    // position within row (8 lanes/row)
    const int grp   = lane >> 3;   // which of the 4 rows this warp handles
    const int gwarp = (blockIdx.x * blockDim.x + threadIdx.x) >> 5;
    const int nwarps= (gridDim.x * blockDim.x) >> 5;

    // Per-lane weights: columns 8*sub .. 8*sub+7 of [x | sin(x)] features.
    const ull* ws = (const ull*)w_sum;
    const ull* wp = (const ull*)w_prod;
    ull wsx[4], wss[4], wpx[4], wps[4];
    #pragma unroll
    for (int j = 0; j < 4; j++) {
        wsx[j] = ws[sub * 4 + j];
        wss[j] = ws[32 + sub * 4 + j];
        wpx[j] = wp[sub * 4 + j];
        wps[j] = wp[32 + sub * 4 + j];
    }
    const float bias = *b_sum;

    // Broadcast packed constants (register-resident)
    const ull C_INVPI  = pk2( 0.31830988618379067f,  0.31830988618379067f);
    const ull C_MAGIC  = pk2( 12582912.0f,  12582912.0f);   // 1.5*2^23
    const ull C_NMAGIC = pk2(-12582912.0f, -12582912.0f);
    // SLEEF 3-part float pi (12-bit limbs: k*limb exact for k < 2^12)
    const ull P0 = pk2(-3.1414794921875f,            -3.1414794921875f);
    const ull P1 = pk2(-1.1315941810607910156e-04f,  -1.1315941810607910156e-04f);
    const ull P2 = pk2(-1.9841872589410058936e-09f,  -1.9841872589410058936e-09f);
    const ull S0 = pk2( 2.6083159809786593541503e-06f,  2.6083159809786593541503e-06f);
    const ull S1 = pk2(-1.9810690716840117e-04f,        -1.9810690716840117e-04f);
    const ull S2 = pk2( 8.3330778777599334716797e-03f,   8.3330778777599334716797e-03f);
    const ull S3 = pk2(-1.6666659712791442871094e-01f,  -1.6666659712791442871094e-01f);

    for (int r0 = gwarp * 4; r0 < B; r0 += nwarps * 4) {
        const int row = r0 + grp;
        const ull* xr = (const ull*)(x + (size_t)row * 64) + sub * 4;
        const ulonglong2 va = ((const ulonglong2*)xr)[0];   // pairs 0,1
        const ulonglong2 vb = ((const ulonglong2*)xr)[1];   // pairs 2,3
        const ull p[4] = { va.x, va.y, vb.x, vb.y };

        ull   lin = 0ull;          // packed linear accumulator
        float lg0 = 0.0f, lg1 = 0.0f;  // scalar log accumulators (lo/hi halves)

        #pragma unroll
        for (int j = 0; j < 4; j++) {
            const ull v = p[j];

            // ---- packed sin ----
            const ull t = fma2(v, C_INVPI, C_MAGIC);   // round(x/pi) in mantissa
            float t0, t1; upk2(t, t0, t1);
            const unsigned q0 = (unsigned)__float_as_int(t0);
            const unsigned q1 = (unsigned)__float_as_int(t1);
            const ull kk = add2(t, C_NMAGIC);          // k = round(x/pi)

            ull r = fma2(kk, P0, v);                   // 3-part Cody-Waite
            r = fma2(kk, P1, r);
            r = fma2(kk, P2, r);

            const ull s = mul2(r, r);
            ull u = S0;
            u = fma2(u, s, S1);
            u = fma2(u, s, S2);
            u = fma2(u, s, S3);
            u = fma2(u, mul2(s, r), r);                // sin(r), sign of r

            // apply (-1)^k by XORing parity into each half's sign bit
            const ull mask = (ull)(q0 << 31) | ((ull)(q1 << 31) << 32);
            const ull us = u ^ mask;                   // = sin(x)

            // ---- linear dot (packed) ----
            lin = fma2(v,  wsx[j], lin);
            lin = fma2(us, wss[j], lin);

            // ---- log dot (scalar halves; MUFU.LG2 gets free |.|) ----
            float v0, v1, u0, u1, wx0, wx1, wsn0, wsn1;
            upk2(v,      v0,  v1);
            upk2(us,     u0,  u1);
            upk2(wpx[j], wx0, wx1);
            upk2(wps[j], wsn0, wsn1);
            lg0 = fmaf(__log2f(fabsf(v0)), wx0,  lg0);
            lg1 = fmaf(__log2f(fabsf(v1)), wx1,  lg1);
            lg0 = fmaf(__log2f(fabsf(u0)), wsn0, lg0);
            lg1 = fmaf(__log2f(fabsf(u1)), wsn1, lg1);
        }

        // horizontal add within packed pair, then 3-level butterfly over 8 lanes
        float l0, l1;
        upk2(lin, l0, l1);
        float lin_s = l0 + l1;
        float lg_s  = lg0 + lg1;
        #pragma unroll
        for (int off = 4; off > 0; off >>= 1) {
            lin_s += __shfl_xor_sync(0xFFFFFFFFu, lin_s, off);
            lg_s  += __shfl_xor_sync(0xFFFFFFFFu, lg_s,  off);
        }

        if (sub == 0) {
            out[row] = make_float2(lin_s + bias, exp2f(lg_s));
        }
    }
}

extern "C" void kernel_launch(void* const* d_in, const int* in_sizes, int n_in,
                              void* d_out, int out_size)
{
    const float* x      = (const float*)d_in[0];
    const float* w_sum  = (const float*)d_in[1];
    const float* b_sum  = (const float*)d_in[2];
    const float* w_prod = (const float*)d_in[3];
    float2* out = (float2*)d_out;

    const int B = in_sizes[0] / 64;   // 1048576

    const int threads = 256;   // 8 warps/block
    const int blocks  = 2048;  // 16384 warps * 4 rows/iter; 16 iters exactly
    myfunc_kernel<<<blocks, threads>>>(x, w_sum, b_sum, w_prod, out, B);
}